// round 1
// baseline (speedup 1.0000x reference)
#include <cuda_runtime.h>
#include <cstddef>

// Problem constants (fixed by the dataset)
#define BSZ 8
#define LSEQ 4096
#define DM 1024
#define NS 64
#define CT 128              // chunk = token tile
#define NC (LSEQ / CT)      // 32 chunks per batch
#define LN_EPS 1e-5f

// ---------------- device scratch (no allocation allowed) ----------------
__device__ float2 g_coef[NS];                 // (a_bar - 1) / a
__device__ float2 g_abar[NS];                 // a_bar
__device__ float2 g_apow[(CT + 1) * NS];      // a_bar^k, k = 0..128, layout [k][n]
__device__ float  g_W[DM * 2 * NS];           // [k][j]: j<64 -> Re(b_bar[j][k]), j>=64 -> Im
__device__ float2 g_h[(size_t)BSZ * LSEQ * NS];   // local (within-chunk) scanned states, 16 MB
__device__ float2 g_carry[BSZ * NC * NS];     // carry-in state per chunk

__device__ __forceinline__ float2 cmul(float2 a, float2 b) {
    return make_float2(a.x * b.x - a.y * b.y, a.x * b.y + a.y * b.x);
}

// ---------------- K0a: per-state constants + powers table ----------------
__global__ void k0a_consts(const float* __restrict__ lnr, const float* __restrict__ imag) {
    int n = threadIdx.x;
    if (n >= NS) return;
    float ar = -expf(lnr[n]);
    float ai = imag[n];
    float e  = expf(ar);
    float2 abar = make_float2(e * cosf(ai), e * sinf(ai));
    g_abar[n] = abar;
    // coef = (abar - 1) / a  (complex division by a = ar + i*ai)
    float2 num = make_float2(abar.x - 1.0f, abar.y);
    float inv = 1.0f / (ar * ar + ai * ai);
    g_coef[n] = make_float2((num.x * ar + num.y * ai) * inv,
                            (num.y * ar - num.x * ai) * inv);
    float2 p = make_float2(1.0f, 0.0f);
    for (int k = 0; k <= CT; k++) {
        g_apow[k * NS + n] = p;
        p = cmul(p, abar);
    }
}

// ---------------- K0b: build input-projection weight W [1024][128] ----------------
__global__ void k0b_weights(const float* __restrict__ Bm) {
    int k = blockIdx.x;      // 0..1023
    int j = threadIdx.x;     // 0..127
    int n = j & 63;
    float2 c = g_coef[n];
    float bv = Bm[n * DM + k];
    g_W[k * 128 + j] = (j < NS ? c.x : c.y) * bv;
}

// ---------------- K1: Bu GEMM (128 tok x 128 cols, K=1024) + local scan ----------------
#define KT 16
#define K1_SMEM ((KT * 132 + KT * 128 + CT * 128) * 4)   // As + Bs + Bu = 82176 B

__global__ __launch_bounds__(256, 2) void k1_bu_scan(const float* __restrict__ u) {
    extern __shared__ float smem[];
    float* As = smem;                         // [KT][132]  (k-major, padded)
    float* Bs = smem + KT * 132;              // [KT][128]
    float* Bu = smem + KT * 132 + KT * 128;   // [128 tok][128 col]

    int chunk = blockIdx.x, b = blockIdx.y;
    int tid = threadIdx.x;
    int tx = tid & 15, ty = tid >> 4;

    const float* up = u + ((size_t)b * LSEQ + (size_t)chunk * CT) * DM;

    float acc[8][8];
#pragma unroll
    for (int i = 0; i < 8; i++)
#pragma unroll
        for (int j = 0; j < 8; j++) acc[i][j] = 0.0f;

    int tA = tid >> 2;            // 0..63
    int kA = (tid & 3) * 4;       // 0,4,8,12
    int rB = tid >> 5;            // 0..7
    int cB = (tid & 31) * 4;      // 0..124

    for (int k0 = 0; k0 < DM; k0 += KT) {
        // load U tile transposed into As[k][t]
#pragma unroll
        for (int p = 0; p < 2; p++) {
            int t = tA + p * 64;
            float4 v = *(const float4*)(up + (size_t)t * DM + k0 + kA);
            As[(kA + 0) * 132 + t] = v.x;
            As[(kA + 1) * 132 + t] = v.y;
            As[(kA + 2) * 132 + t] = v.z;
            As[(kA + 3) * 132 + t] = v.w;
        }
        // load W tile Bs[k][c]
#pragma unroll
        for (int p = 0; p < 2; p++) {
            int r = rB + p * 8;
            *(float4*)&Bs[r * 128 + cB] = *(const float4*)(g_W + (size_t)(k0 + r) * 128 + cB);
        }
        __syncthreads();
#pragma unroll
        for (int k = 0; k < KT; k++) {
            float4 a0 = *(float4*)(As + k * 132 + ty * 8);
            float4 a1 = *(float4*)(As + k * 132 + ty * 8 + 4);
            float4 b0 = *(float4*)(Bs + k * 128 + tx * 8);
            float4 b1 = *(float4*)(Bs + k * 128 + tx * 8 + 4);
            float av[8] = {a0.x, a0.y, a0.z, a0.w, a1.x, a1.y, a1.z, a1.w};
            float bv[8] = {b0.x, b0.y, b0.z, b0.w, b1.x, b1.y, b1.z, b1.w};
#pragma unroll
            for (int i = 0; i < 8; i++)
#pragma unroll
                for (int j = 0; j < 8; j++)
                    acc[i][j] = fmaf(av[i], bv[j], acc[i][j]);
        }
        __syncthreads();
    }

    // stage Bu into smem
#pragma unroll
    for (int i = 0; i < 8; i++) {
        float4 w0 = make_float4(acc[i][0], acc[i][1], acc[i][2], acc[i][3]);
        float4 w1 = make_float4(acc[i][4], acc[i][5], acc[i][6], acc[i][7]);
        *(float4*)(Bu + (ty * 8 + i) * 128 + tx * 8)     = w0;
        *(float4*)(Bu + (ty * 8 + i) * 128 + tx * 8 + 4) = w1;
    }
    __syncthreads();

    // local sequential scan: h_t = a_bar * h_{t-1} + Bu_t  (64 states, 1 thread each)
    if (tid < NS) {
        int n = tid;
        float2 ab = g_abar[n];
        float hr = 0.0f, hi = 0.0f;
        float2* outp = g_h + ((size_t)b * LSEQ + (size_t)chunk * CT) * NS + n;
#pragma unroll 4
        for (int t = 0; t < CT; t++) {
            float xr = Bu[t * 128 + n];
            float xi = Bu[t * 128 + n + 64];
            float nr = fmaf(ab.x, hr, fmaf(-ab.y, hi, xr));
            float ni = fmaf(ab.x, hi, fmaf( ab.y, hr, xi));
            hr = nr; hi = ni;
            outp[(size_t)t * NS] = make_float2(hr, hi);
        }
    }
}

// ---------------- K2: cross-chunk carry scan ----------------
__global__ void k2_carry() {
    int tid = threadIdx.x;       // 512 threads, 1 block
    int b = tid >> 6, n = tid & 63;
    float2 p = g_apow[CT * NS + n];     // a_bar^128
    float2 H = make_float2(0.0f, 0.0f);
    for (int c = 0; c < NC; c++) {
        g_carry[((size_t)b * NC + c) * NS + n] = H;
        float2 S = g_h[((size_t)b * LSEQ + (size_t)c * CT + CT - 1) * NS + n];
        float2 t = cmul(p, H);
        H = make_float2(t.x + S.x, t.y + S.y);
    }
}

// ---------------- K3: readout GEMM + residual, writes x to d_out ----------------
#define K3_SMEM ((2 * 64 * 132 + 128) * 4)   // Rs + Cs + Hs = 68096 B

__global__ __launch_bounds__(256, 2) void k3_readout(const float* __restrict__ u,
                                                     const float* __restrict__ Cm,
                                                     const float* __restrict__ Dv,
                                                     float* __restrict__ xout) {
    extern __shared__ float smem[];
    float* Rs = smem;               // [64 n][132]  Re(h) k-major
    float* Cs = smem + 64 * 132;    // [64 k][132]  C tile k-major
    float* Hs = smem + 2 * 64 * 132; // [128]: Hr[64], Hi[64]

    int dt = blockIdx.x, chunk = blockIdx.y, b = blockIdx.z;
    int tid = threadIdx.x;
    int tx = tid & 15, ty = tid >> 4;

    if (tid < NS) {
        float2 H = g_carry[((size_t)b * NC + chunk) * NS + tid];
        Hs[tid] = H.x;
        Hs[64 + tid] = H.y;
    }
    __syncthreads();

    // build Rs[n][t] = Re(a^{t+1} * H) + Re(l_t)
    {
        int n = tid & 63, tq = tid >> 6;   // 4 token groups
        float Hr = Hs[n], Hi = Hs[64 + n];
        const float2* hp = g_h + ((size_t)b * LSEQ + (size_t)chunk * CT) * NS;
        for (int t = tq; t < CT; t += 4) {
            float2 lv = hp[(size_t)t * NS + n];
            float2 pw = g_apow[(t + 1) * NS + n];
            Rs[n * 132 + t] = fmaf(pw.x, Hr, fmaf(-pw.y, Hi, lv.x));
        }
    }
    // build Cs[k][d'] = C[(dt*128+d')][k]
    {
        int d = tid >> 1;
        int kh = (tid & 1) * 32;
        const float* cp = Cm + ((size_t)dt * 128 + d) * NS + kh;
#pragma unroll
        for (int q = 0; q < 8; q++) {
            float4 v = *(const float4*)(cp + q * 4);
            Cs[(kh + q * 4 + 0) * 132 + d] = v.x;
            Cs[(kh + q * 4 + 1) * 132 + d] = v.y;
            Cs[(kh + q * 4 + 2) * 132 + d] = v.z;
            Cs[(kh + q * 4 + 3) * 132 + d] = v.w;
        }
    }
    __syncthreads();

    float acc[8][8];
#pragma unroll
    for (int i = 0; i < 8; i++)
#pragma unroll
        for (int j = 0; j < 8; j++) acc[i][j] = 0.0f;

#pragma unroll 8
    for (int k = 0; k < NS; k++) {
        float4 a0 = *(float4*)(Rs + k * 132 + ty * 8);
        float4 a1 = *(float4*)(Rs + k * 132 + ty * 8 + 4);
        float4 b0 = *(float4*)(Cs + k * 132 + tx * 8);
        float4 b1 = *(float4*)(Cs + k * 132 + tx * 8 + 4);
        float av[8] = {a0.x, a0.y, a0.z, a0.w, a1.x, a1.y, a1.z, a1.w};
        float bv[8] = {b0.x, b0.y, b0.z, b0.w, b1.x, b1.y, b1.z, b1.w};
#pragma unroll
        for (int i = 0; i < 8; i++)
#pragma unroll
            for (int j = 0; j < 8; j++)
                acc[i][j] = fmaf(av[i], bv[j], acc[i][j]);
    }

    // epilogue: x = u*(1+D) + y
    const float* up = u + ((size_t)b * LSEQ + (size_t)chunk * CT) * DM + (size_t)dt * 128;
    float* op = xout + ((size_t)b * LSEQ + (size_t)chunk * CT) * DM + (size_t)dt * 128;
#pragma unroll
    for (int i = 0; i < 8; i++) {
        int t = ty * 8 + i;
#pragma unroll
        for (int j4 = 0; j4 < 8; j4 += 4) {
            int dd = tx * 8 + j4;
            float4 uu = *(const float4*)(up + (size_t)t * DM + dd);
            float4 D4 = *(const float4*)(Dv + (size_t)dt * 128 + dd);
            float4 x;
            x.x = fmaf(uu.x, 1.0f + D4.x, acc[i][j4 + 0]);
            x.y = fmaf(uu.y, 1.0f + D4.y, acc[i][j4 + 1]);
            x.z = fmaf(uu.z, 1.0f + D4.z, acc[i][j4 + 2]);
            x.w = fmaf(uu.w, 1.0f + D4.w, acc[i][j4 + 3]);
            *(float4*)(op + (size_t)t * DM + dd) = x;
        }
    }
}

// ---------------- K4: LayerNorm in place over d_out ----------------
__global__ __launch_bounds__(128) void k4_ln(float* __restrict__ x,
                                             const float* __restrict__ gamma,
                                             const float* __restrict__ beta) {
    __shared__ float ws[4], ws2[4];
    size_t tok = blockIdx.x;
    float* p = x + tok * DM;
    int tid = threadIdx.x;   // 128
    int d0 = tid * 8;
    float4 v0 = *(float4*)(p + d0);
    float4 v1 = *(float4*)(p + d0 + 4);
    float s  = v0.x + v0.y + v0.z + v0.w + v1.x + v1.y + v1.z + v1.w;
    float s2 = v0.x * v0.x + v0.y * v0.y + v0.z * v0.z + v0.w * v0.w
             + v1.x * v1.x + v1.y * v1.y + v1.z * v1.z + v1.w * v1.w;
#pragma unroll
    for (int o = 16; o > 0; o >>= 1) {
        s  += __shfl_xor_sync(0xffffffffu, s, o);
        s2 += __shfl_xor_sync(0xffffffffu, s2, o);
    }
    int w = tid >> 5;
    if ((tid & 31) == 0) { ws[w] = s; ws2[w] = s2; }
    __syncthreads();
    s  = ws[0] + ws[1] + ws[2] + ws[3];
    s2 = ws2[0] + ws2[1] + ws2[2] + ws2[3];
    float mu = s * (1.0f / DM);
    float var = s2 * (1.0f / DM) - mu * mu;
    float rstd = rsqrtf(var + LN_EPS);
    float4 g0 = *(const float4*)(gamma + d0);
    float4 g1 = *(const float4*)(gamma + d0 + 4);
    float4 b0 = *(const float4*)(beta + d0);
    float4 b1 = *(const float4*)(beta + d0 + 4);
    float4 o0, o1;
    o0.x = fmaf((v0.x - mu) * rstd, g0.x, b0.x);
    o0.y = fmaf((v0.y - mu) * rstd, g0.y, b0.y);
    o0.z = fmaf((v0.z - mu) * rstd, g0.z, b0.z);
    o0.w = fmaf((v0.w - mu) * rstd, g0.w, b0.w);
    o1.x = fmaf((v1.x - mu) * rstd, g1.x, b1.x);
    o1.y = fmaf((v1.y - mu) * rstd, g1.y, b1.y);
    o1.z = fmaf((v1.z - mu) * rstd, g1.z, b1.z);
    o1.w = fmaf((v1.w - mu) * rstd, g1.w, b1.w);
    *(float4*)(p + d0)     = o0;
    *(float4*)(p + d0 + 4) = o1;
}

// ---------------- launch ----------------
extern "C" void kernel_launch(void* const* d_in, const int* in_sizes, int n_in,
                              void* d_out, int out_size) {
    const float* u     = (const float*)d_in[0];
    const float* lnr   = (const float*)d_in[1];
    const float* imagv = (const float*)d_in[2];
    const float* Bm    = (const float*)d_in[3];
    const float* Cm    = (const float*)d_in[4];
    const float* Dv    = (const float*)d_in[5];
    const float* gamma = (const float*)d_in[6];
    const float* beta  = (const float*)d_in[7];
    float* out = (float*)d_out;

    cudaFuncSetAttribute(k1_bu_scan, cudaFuncAttributeMaxDynamicSharedMemorySize, K1_SMEM);
    cudaFuncSetAttribute(k3_readout, cudaFuncAttributeMaxDynamicSharedMemorySize, K3_SMEM);

    k0a_consts<<<1, 64>>>(lnr, imagv);
    k0b_weights<<<DM, 128>>>(Bm);
    k1_bu_scan<<<dim3(NC, BSZ), 256, K1_SMEM>>>(u);
    k2_carry<<<1, 512>>>();
    k3_readout<<<dim3(8, NC, BSZ), 256, K3_SMEM>>>(u, Cm, Dv, out);
    k4_ln<<<BSZ * LSEQ, 128>>>(out, gamma, beta);
}

// round 3
// speedup vs baseline: 1.6472x; 1.6472x over previous
#include <cuda_runtime.h>
#include <cstdint>
#include <cstddef>

// Problem constants (fixed by the dataset)
#define BSZ 8
#define LSEQ 4096
#define DM 1024
#define NS 64
#define CT 128
#define NC (LSEQ / CT)
#define LN_EPS 1e-5f

// ---------------- device scratch ----------------
__device__ float2 g_abar[NS];
__device__ float2 g_coef[NS];
__device__ float2 g_apow[(CT + 1) * NS];
__device__ float  g_W[128 * DM];                  // [j][k], tf32-rounded bits, j<64 Re, j>=64 Im
__device__ float2 g_h[(size_t)BSZ * LSEQ * NS];   // within-chunk scanned states
__device__ float2 g_last[BSZ * NC * NS];          // chunk-final local states
__device__ float2 g_carry[BSZ * NC * NS];         // carry-in per chunk

__device__ __forceinline__ float2 cmul(float2 a, float2 b) {
    return make_float2(a.x * b.x - a.y * b.y, a.x * b.y + a.y * b.x);
}
__device__ __forceinline__ uint32_t f2tf(float f) {
    uint32_t r;
    asm("cvt.rna.tf32.f32 %0, %1;" : "=r"(r) : "f"(f));
    return r;
}
__device__ __forceinline__ void mma8(float4& d, const uint32_t* a, const uint32_t* b) {
    asm volatile(
        "mma.sync.aligned.m16n8k8.row.col.f32.tf32.tf32.f32 "
        "{%0,%1,%2,%3},{%4,%5,%6,%7},{%8,%9},{%0,%1,%2,%3};\n"
        : "+f"(d.x), "+f"(d.y), "+f"(d.z), "+f"(d.w)
        : "r"(a[0]), "r"(a[1]), "r"(a[2]), "r"(a[3]), "r"(b[0]), "r"(b[1]));
}

// ---------------- K0a: constants + powers ----------------
__global__ void k0a_consts(const float* __restrict__ lnr, const float* __restrict__ imag) {
    int n = threadIdx.x;
    if (n >= NS) return;
    float ar = -expf(lnr[n]);
    float ai = imag[n];
    float e  = expf(ar);
    float2 abar = make_float2(e * cosf(ai), e * sinf(ai));
    g_abar[n] = abar;
    float2 num = make_float2(abar.x - 1.0f, abar.y);
    float inv = 1.0f / (ar * ar + ai * ai);
    g_coef[n] = make_float2((num.x * ar + num.y * ai) * inv,
                            (num.y * ar - num.x * ai) * inv);
    float2 p = make_float2(1.0f, 0.0f);
    for (int k = 0; k <= CT; k++) {
        g_apow[k * NS + n] = p;
        p = cmul(p, abar);
    }
}

// ---------------- K0b: W[j][k] = tf32(coef_part(j) * B[n][k]) ----------------
__global__ void k0b_weights(const float* __restrict__ Bm) {
    int j = blockIdx.x;          // 0..127
    int n = j & 63;
    float2 c = g_coef[n];
    float s = (j < NS) ? c.x : c.y;
    for (int k = threadIdx.x; k < DM; k += blockDim.x)
        g_W[(size_t)j * DM + k] = __uint_as_float(f2tf(s * Bm[(size_t)n * DM + k]));
}

// ---------------- K1: tf32 MMA Bu-GEMM (128x128, K=1024) + local scan ----------------
#define KC 32
#define ASTR 36
// smem words: As(2x128x36)=9216 + Bs(2x128x36)=9216 + Bu(128x128)=16384 = 34816 words
#define K1_SMEM (34816 * 4)

__global__ __launch_bounds__(256, 1) void k1_bu_scan(const float* __restrict__ u) {
    extern __shared__ float sm[];
    float* As0 = sm;
    float* As1 = sm + 128 * ASTR;
    float* Bs0 = sm + 2 * 128 * ASTR;
    float* Bs1 = sm + 3 * 128 * ASTR;
    float* Bu  = sm + 4 * 128 * ASTR;

    int chunk = blockIdx.x, b = blockIdx.y;
    int tid = threadIdx.x;
    int lane = tid & 31, warp = tid >> 5;
    int wm = warp & 1, wn = warp >> 1;
    int m0 = wm * 64, n0 = wn * 32;
    int lq = lane >> 2, cq = lane & 3;

    const float* up = u + ((size_t)(b * LSEQ + chunk * CT)) * DM;

    float4 acc[4][4];
#pragma unroll
    for (int i = 0; i < 4; i++)
#pragma unroll
        for (int j = 0; j < 4; j++) acc[i][j] = make_float4(0.f, 0.f, 0.f, 0.f);

    float4 rA[4], rB[4];
    int lrow[4], lkq[4];
#pragma unroll
    for (int i = 0; i < 4; i++) {
        int lin = tid + i * 256;
        lrow[i] = lin >> 3;
        lkq[i] = (lin & 7) * 4;
    }

    // preload stage 0
#pragma unroll
    for (int i = 0; i < 4; i++) {
        rA[i] = *(const float4*)(up + (size_t)lrow[i] * DM + lkq[i]);
        rB[i] = *(const float4*)(g_W + (size_t)lrow[i] * DM + lkq[i]);
    }
#pragma unroll
    for (int i = 0; i < 4; i++) {
        uint4 a;
        a.x = f2tf(rA[i].x); a.y = f2tf(rA[i].y); a.z = f2tf(rA[i].z); a.w = f2tf(rA[i].w);
        *(uint4*)(As0 + lrow[i] * ASTR + lkq[i]) = a;
        *(float4*)(Bs0 + lrow[i] * ASTR + lkq[i]) = rB[i];
    }
    __syncthreads();

    for (int s = 0; s < DM / KC; s++) {
        float* Ac = (s & 1) ? As1 : As0;
        float* Bc = (s & 1) ? Bs1 : Bs0;
        float* An = (s & 1) ? As0 : As1;
        float* Bn = (s & 1) ? Bs0 : Bs1;
        if (s + 1 < DM / KC) {
            int k0 = (s + 1) * KC;
#pragma unroll
            for (int i = 0; i < 4; i++) {
                rA[i] = *(const float4*)(up + (size_t)lrow[i] * DM + k0 + lkq[i]);
                rB[i] = *(const float4*)(g_W + (size_t)lrow[i] * DM + k0 + lkq[i]);
            }
        }
        const uint32_t* Au = (const uint32_t*)Ac;
        const uint32_t* Bv = (const uint32_t*)Bc;
#pragma unroll
        for (int ks = 0; ks < 4; ks++) {
            int kb = ks * 8;
            uint32_t af[4][4], bf[4][2];
#pragma unroll
            for (int mt = 0; mt < 4; mt++) {
                int r = m0 + mt * 16 + lq;
                af[mt][0] = Au[r * ASTR + kb + cq];
                af[mt][1] = Au[(r + 8) * ASTR + kb + cq];
                af[mt][2] = Au[r * ASTR + kb + cq + 4];
                af[mt][3] = Au[(r + 8) * ASTR + kb + cq + 4];
            }
#pragma unroll
            for (int nt = 0; nt < 4; nt++) {
                int c = n0 + nt * 8 + lq;
                bf[nt][0] = Bv[c * ASTR + kb + cq];
                bf[nt][1] = Bv[c * ASTR + kb + cq + 4];
            }
#pragma unroll
            for (int mt = 0; mt < 4; mt++)
#pragma unroll
                for (int nt = 0; nt < 4; nt++)
                    mma8(acc[mt][nt], af[mt], bf[nt]);
        }
        if (s + 1 < DM / KC) {
#pragma unroll
            for (int i = 0; i < 4; i++) {
                uint4 a;
                a.x = f2tf(rA[i].x); a.y = f2tf(rA[i].y); a.z = f2tf(rA[i].z); a.w = f2tf(rA[i].w);
                *(uint4*)(An + lrow[i] * ASTR + lkq[i]) = a;
                *(float4*)(Bn + lrow[i] * ASTR + lkq[i]) = rB[i];
            }
        }
        __syncthreads();
    }

    // write Bu tile to smem
#pragma unroll
    for (int mt = 0; mt < 4; mt++) {
        int r = m0 + mt * 16 + lq;
#pragma unroll
        for (int nt = 0; nt < 4; nt++) {
            int c = n0 + nt * 8 + cq * 2;
            *(float2*)(Bu + r * 128 + c)       = make_float2(acc[mt][nt].x, acc[mt][nt].y);
            *(float2*)(Bu + (r + 8) * 128 + c) = make_float2(acc[mt][nt].z, acc[mt][nt].w);
        }
    }
    __syncthreads();

    // local scan: 64 states, 1 thread each
    if (tid < NS) {
        float2 ab = g_abar[tid];
        float hr = 0.0f, hi = 0.0f;
        float2* outp = g_h + ((size_t)(b * LSEQ + chunk * CT)) * NS + tid;
#pragma unroll 4
        for (int t = 0; t < CT; t++) {
            float xr = Bu[t * 128 + tid];
            float xi = Bu[t * 128 + 64 + tid];
            float nr = fmaf(ab.x, hr, fmaf(-ab.y, hi, xr));
            float ni = fmaf(ab.x, hi, fmaf( ab.y, hr, xi));
            hr = nr; hi = ni;
            outp[(size_t)t * NS] = make_float2(hr, hi);
        }
        g_last[(b * NC + chunk) * NS + tid] = make_float2(hr, hi);
    }
}

// ---------------- K2: cross-chunk carry scan (prefetched, MLP=32) ----------------
__global__ void k2_carry() {
    int tid = threadIdx.x;       // 512 threads, 1 block
    int b = tid >> 6, n = tid & 63;
    float2 p = g_apow[CT * NS + n];
    float2 S[NC];
#pragma unroll
    for (int c = 0; c < NC; c++) S[c] = g_last[(b * NC + c) * NS + n];
    float2 H = make_float2(0.0f, 0.0f);
#pragma unroll
    for (int c = 0; c < NC; c++) {
        g_carry[(b * NC + c) * NS + n] = H;
        float2 t = cmul(p, H);
        H = make_float2(t.x + S[c].x, t.y + S[c].y);
    }
}

// ---------------- K3: tf32 MMA readout + residual + fused LayerNorm ----------------
#define XSTR 1032
#define CSTR 68
// smem words: X(32x1032)=33024 + Cs(128x68)=8704 + Rs(32x68)=2176 = 43904 words
#define K3_SMEM (43904 * 4)

__global__ __launch_bounds__(256, 1) void k3_readout(const float* __restrict__ u,
                                                     const float* __restrict__ Cm,
                                                     const float* __restrict__ Dv,
                                                     const float* __restrict__ gamma,
                                                     const float* __restrict__ beta,
                                                     float* __restrict__ out) {
    extern __shared__ float sm[];
    float* X  = sm;
    float* Cs = sm + 32 * XSTR;
    float* Rs = sm + 32 * XSTR + 128 * CSTR;

    int g = blockIdx.x, b = blockIdx.y;
    int chunk = g >> 2, t0 = (g & 3) * 32;
    int tid = threadIdx.x;
    int lane = tid & 31, warp = tid >> 5;
    size_t tokbase = (size_t)b * LSEQ + (size_t)chunk * CT + t0;

    // build Rs[t][n] = tf32(Re(a^{t0+t+1} * H + h_local))
    {
        int n = tid & 63, tq = tid >> 6;
        float2 H = g_carry[(b * NC + chunk) * NS + n];
        const float2* hp = g_h + tokbase * NS;
        for (int t = tq; t < 32; t += 4) {
            float2 lv = hp[(size_t)t * NS + n];
            float2 pw = g_apow[(t0 + t + 1) * NS + n];
            float v = fmaf(pw.x, H.x, fmaf(-pw.y, H.y, lv.x));
            Rs[t * CSTR + n] = __uint_as_float(f2tf(v));
        }
    }

    int wm = warp & 1, wn = warp >> 1;
    int m0 = wm * 16, n0 = wn * 32;
    int lq = lane >> 2, cq = lane & 3;

    for (int nd = 0; nd < 8; nd++) {
        int d0 = nd * 128;
        __syncthreads();   // previous mma done (and Rs ready on first iter)
        // load C chunk: Cs[d'][k] = tf32(Cm[d0+d'][k])
#pragma unroll
        for (int i = 0; i < 8; i++) {
            int lin = tid + i * 256;
            int row = lin >> 4;
            int kq = (lin & 15) * 4;
            float4 v = *(const float4*)(Cm + (size_t)(d0 + row) * NS + kq);
            uint4 t;
            t.x = f2tf(v.x); t.y = f2tf(v.y); t.z = f2tf(v.z); t.w = f2tf(v.w);
            *(uint4*)(Cs + row * CSTR + kq) = t;
        }
        __syncthreads();

        float4 acc[4];
#pragma unroll
        for (int nt = 0; nt < 4; nt++) acc[nt] = make_float4(0.f, 0.f, 0.f, 0.f);

        const uint32_t* Ru = (const uint32_t*)Rs;
        const uint32_t* Cu = (const uint32_t*)Cs;
#pragma unroll
        for (int ks = 0; ks < 8; ks++) {
            int kb = ks * 8;
            uint32_t af[4];
            af[0] = Ru[(m0 + lq) * CSTR + kb + cq];
            af[1] = Ru[(m0 + lq + 8) * CSTR + kb + cq];
            af[2] = Ru[(m0 + lq) * CSTR + kb + cq + 4];
            af[3] = Ru[(m0 + lq + 8) * CSTR + kb + cq + 4];
#pragma unroll
            for (int nt = 0; nt < 4; nt++) {
                uint32_t bf[2];
                bf[0] = Cu[(n0 + nt * 8 + lq) * CSTR + kb + cq];
                bf[1] = Cu[(n0 + nt * 8 + lq) * CSTR + kb + cq + 4];
                mma8(acc[nt], af, bf);
            }
        }
        // epilogue: X = y + u*(1+D)
#pragma unroll
        for (int nt = 0; nt < 4; nt++) {
            int d = d0 + n0 + nt * 8 + cq * 2;
            int r1 = m0 + lq, r2 = r1 + 8;
            float2 u1 = *(const float2*)(u + (tokbase + r1) * DM + d);
            float2 u2 = *(const float2*)(u + (tokbase + r2) * DM + d);
            float2 D2 = *(const float2*)(Dv + d);
            *(float2*)(X + r1 * XSTR + d) =
                make_float2(fmaf(u1.x, 1.0f + D2.x, acc[nt].x), fmaf(u1.y, 1.0f + D2.y, acc[nt].y));
            *(float2*)(X + r2 * XSTR + d) =
                make_float2(fmaf(u2.x, 1.0f + D2.x, acc[nt].z), fmaf(u2.y, 1.0f + D2.y, acc[nt].w));
        }
    }
    __syncthreads();

    // fused LayerNorm over the 32 rows in X, write out
    for (int q = 0; q < 4; q++) {
        int r = warp * 4 + q;
        float s = 0.f, s2 = 0.f;
#pragma unroll
        for (int i = 0; i < 8; i++) {
            float4 v = *(float4*)(X + r * XSTR + (lane + i * 32) * 4);
            s  += v.x + v.y + v.z + v.w;
            s2 += v.x * v.x + v.y * v.y + v.z * v.z + v.w * v.w;
        }
#pragma unroll
        for (int o = 16; o > 0; o >>= 1) {
            s  += __shfl_xor_sync(0xffffffffu, s, o);
            s2 += __shfl_xor_sync(0xffffffffu, s2, o);
        }
        float mu = s * (1.0f / DM);
        float var = s2 * (1.0f / DM) - mu * mu;
        float rstd = rsqrtf(var + LN_EPS);
        float* op = out + (tokbase + r) * DM;
#pragma unroll
        for (int i = 0; i < 8; i++) {
            int d = (lane + i * 32) * 4;
            float4 v = *(float4*)(X + r * XSTR + d);
            float4 gg = *(const float4*)(gamma + d);
            float4 bb = *(const float4*)(beta + d);
            float4 o;
            o.x = fmaf((v.x - mu) * rstd, gg.x, bb.x);
            o.y = fmaf((v.y - mu) * rstd, gg.y, bb.y);
            o.z = fmaf((v.z - mu) * rstd, gg.z, bb.z);
            o.w = fmaf((v.w - mu) * rstd, gg.w, bb.w);
            *(float4*)(op + d) = o;
        }
    }
}

// ---------------- launch ----------------
extern "C" void kernel_launch(void* const* d_in, const int* in_sizes, int n_in,
                              void* d_out, int out_size) {
    const float* u     = (const float*)d_in[0];
    const float* lnr   = (const float*)d_in[1];
    const float* imagv = (const float*)d_in[2];
    const float* Bm    = (const float*)d_in[3];
    const float* Cm    = (const float*)d_in[4];
    const float* Dv    = (const float*)d_in[5];
    const float* gamma = (const float*)d_in[6];
    const float* beta  = (const float*)d_in[7];
    float* out = (float*)d_out;

    cudaFuncSetAttribute(k1_bu_scan, cudaFuncAttributeMaxDynamicSharedMemorySize, K1_SMEM);
    cudaFuncSetAttribute(k3_readout, cudaFuncAttributeMaxDynamicSharedMemorySize, K3_SMEM);

    k0a_consts<<<1, 64>>>(lnr, imagv);
    k0b_weights<<<128, 256>>>(Bm);
    k1_bu_scan<<<dim3(NC, BSZ), 256, K1_SMEM>>>(u);
    k2_carry<<<1, 512>>>();
    // one block per 32 tokens: grid.x = NC*4 = 128 token-groups per batch
    k3_readout<<<dim3(NC * 4, BSZ), 256, K3_SMEM>>>(u, Cm, Dv, gamma, beta, out);
}

// round 4
// speedup vs baseline: 1.9914x; 1.2090x over previous
#include <cuda_runtime.h>
#include <cstdint>
#include <cstddef>

// Problem constants (fixed by the dataset)
#define BSZ 8
#define LSEQ 4096
#define DM 1024
#define NS 64
#define CT 128
#define NC (LSEQ / CT)
#define LN_EPS 1e-5f

// ---------------- device scratch ----------------
__device__ float2 g_abar[NS];
__device__ float2 g_coef[NS];
__device__ float2 g_apow[(CT + 1) * NS];
__device__ float  g_W[128 * DM];                  // [j][k], tf32-rounded bits, j<64 Re, j>=64 Im
__device__ float2 g_h[(size_t)BSZ * LSEQ * NS];   // within-chunk scanned states
__device__ float2 g_last[BSZ * NC * NS];          // chunk-final local states
__device__ float2 g_carry[BSZ * NC * NS];         // carry-in per chunk

__device__ __forceinline__ float2 cmul(float2 a, float2 b) {
    return make_float2(a.x * b.x - a.y * b.y, a.x * b.y + a.y * b.x);
}
__device__ __forceinline__ uint32_t f2tf(float f) {
    uint32_t r;
    asm("cvt.rna.tf32.f32 %0, %1;" : "=r"(r) : "f"(f));
    return r;
}
__device__ __forceinline__ void mma8(float4& d, const uint32_t* a, const uint32_t* b) {
    asm volatile(
        "mma.sync.aligned.m16n8k8.row.col.f32.tf32.tf32.f32 "
        "{%0,%1,%2,%3},{%4,%5,%6,%7},{%8,%9},{%0,%1,%2,%3};\n"
        : "+f"(d.x), "+f"(d.y), "+f"(d.z), "+f"(d.w)
        : "r"(a[0]), "r"(a[1]), "r"(a[2]), "r"(a[3]), "r"(b[0]), "r"(b[1]));
}

// ---------------- K0a: constants + powers ----------------
__global__ void k0a_consts(const float* __restrict__ lnr, const float* __restrict__ imag) {
    int n = threadIdx.x;
    if (n >= NS) return;
    float ar = -expf(lnr[n]);
    float ai = imag[n];
    float e  = expf(ar);
    float2 abar = make_float2(e * cosf(ai), e * sinf(ai));
    g_abar[n] = abar;
    float2 num = make_float2(abar.x - 1.0f, abar.y);
    float inv = 1.0f / (ar * ar + ai * ai);
    g_coef[n] = make_float2((num.x * ar + num.y * ai) * inv,
                            (num.y * ar - num.x * ai) * inv);
    float2 p = make_float2(1.0f, 0.0f);
    for (int k = 0; k <= CT; k++) {
        g_apow[k * NS + n] = p;
        p = cmul(p, abar);
    }
}

// ---------------- K0b: W[j][k] = tf32(coef_part(j) * B[n][k]) ----------------
__global__ void k0b_weights(const float* __restrict__ Bm) {
    int j = blockIdx.x;          // 0..127
    int n = j & 63;
    float2 c = g_coef[n];
    float s = (j < NS) ? c.x : c.y;
    for (int k = threadIdx.x; k < DM; k += blockDim.x)
        g_W[(size_t)j * DM + k] = __uint_as_float(f2tf(s * Bm[(size_t)n * DM + k]));
}

// ---------------- K1: tf32 MMA Bu-GEMM (128x128, K=1024) + local scan ----------------
#define KC 32
#define ASTR 36
// smem words: As(2x128x36)=9216 + Bs(2x128x36)=9216 + Bu(128x128)=16384 = 34816 words
#define K1_SMEM (34816 * 4)

__global__ __launch_bounds__(256, 1) void k1_bu_scan(const float* __restrict__ u) {
    extern __shared__ float sm[];
    float* As0 = sm;
    float* As1 = sm + 128 * ASTR;
    float* Bs0 = sm + 2 * 128 * ASTR;
    float* Bs1 = sm + 3 * 128 * ASTR;
    float* Bu  = sm + 4 * 128 * ASTR;

    int chunk = blockIdx.x, b = blockIdx.y;
    int tid = threadIdx.x;
    int lane = tid & 31, warp = tid >> 5;
    int wm = warp & 1, wn = warp >> 1;
    int m0 = wm * 64, n0 = wn * 32;
    int lq = lane >> 2, cq = lane & 3;

    const float* up = u + ((size_t)(b * LSEQ + chunk * CT)) * DM;

    float4 acc[4][4];
#pragma unroll
    for (int i = 0; i < 4; i++)
#pragma unroll
        for (int j = 0; j < 4; j++) acc[i][j] = make_float4(0.f, 0.f, 0.f, 0.f);

    float4 rA[4], rB[4];
    int lrow[4], lkq[4];
#pragma unroll
    for (int i = 0; i < 4; i++) {
        int lin = tid + i * 256;
        lrow[i] = lin >> 3;
        lkq[i] = (lin & 7) * 4;
    }

    // preload stage 0
#pragma unroll
    for (int i = 0; i < 4; i++) {
        rA[i] = *(const float4*)(up + (size_t)lrow[i] * DM + lkq[i]);
        rB[i] = *(const float4*)(g_W + (size_t)lrow[i] * DM + lkq[i]);
    }
#pragma unroll
    for (int i = 0; i < 4; i++) {
        uint4 a;
        a.x = f2tf(rA[i].x); a.y = f2tf(rA[i].y); a.z = f2tf(rA[i].z); a.w = f2tf(rA[i].w);
        *(uint4*)(As0 + lrow[i] * ASTR + lkq[i]) = a;
        *(float4*)(Bs0 + lrow[i] * ASTR + lkq[i]) = rB[i];
    }
    __syncthreads();

    for (int s = 0; s < DM / KC; s++) {
        float* Ac = (s & 1) ? As1 : As0;
        float* Bc = (s & 1) ? Bs1 : Bs0;
        float* An = (s & 1) ? As0 : As1;
        float* Bn = (s & 1) ? Bs0 : Bs1;
        if (s + 1 < DM / KC) {
            int k0 = (s + 1) * KC;
#pragma unroll
            for (int i = 0; i < 4; i++) {
                rA[i] = *(const float4*)(up + (size_t)lrow[i] * DM + k0 + lkq[i]);
                rB[i] = *(const float4*)(g_W + (size_t)lrow[i] * DM + k0 + lkq[i]);
            }
        }
        const uint32_t* Au = (const uint32_t*)Ac;
        const uint32_t* Bv = (const uint32_t*)Bc;
#pragma unroll
        for (int ks = 0; ks < 4; ks++) {
            int kb = ks * 8;
            uint32_t af[4][4], bf[4][2];
#pragma unroll
            for (int mt = 0; mt < 4; mt++) {
                int r = m0 + mt * 16 + lq;
                af[mt][0] = Au[r * ASTR + kb + cq];
                af[mt][1] = Au[(r + 8) * ASTR + kb + cq];
                af[mt][2] = Au[r * ASTR + kb + cq + 4];
                af[mt][3] = Au[(r + 8) * ASTR + kb + cq + 4];
            }
#pragma unroll
            for (int nt = 0; nt < 4; nt++) {
                int c = n0 + nt * 8 + lq;
                bf[nt][0] = Bv[c * ASTR + kb + cq];
                bf[nt][1] = Bv[c * ASTR + kb + cq + 4];
            }
#pragma unroll
            for (int mt = 0; mt < 4; mt++)
#pragma unroll
                for (int nt = 0; nt < 4; nt++)
                    mma8(acc[mt][nt], af[mt], bf[nt]);
        }
        if (s + 1 < DM / KC) {
#pragma unroll
            for (int i = 0; i < 4; i++) {
                uint4 a;
                a.x = f2tf(rA[i].x); a.y = f2tf(rA[i].y); a.z = f2tf(rA[i].z); a.w = f2tf(rA[i].w);
                *(uint4*)(An + lrow[i] * ASTR + lkq[i]) = a;
                *(float4*)(Bn + lrow[i] * ASTR + lkq[i]) = rB[i];
            }
        }
        __syncthreads();
    }

    // write Bu tile to smem
#pragma unroll
    for (int mt = 0; mt < 4; mt++) {
        int r = m0 + mt * 16 + lq;
#pragma unroll
        for (int nt = 0; nt < 4; nt++) {
            int c = n0 + nt * 8 + cq * 2;
            *(float2*)(Bu + r * 128 + c)       = make_float2(acc[mt][nt].x, acc[mt][nt].y);
            *(float2*)(Bu + (r + 8) * 128 + c) = make_float2(acc[mt][nt].z, acc[mt][nt].w);
        }
    }
    __syncthreads();

    // local scan: 64 states, 1 thread each
    if (tid < NS) {
        float2 ab = g_abar[tid];
        float hr = 0.0f, hi = 0.0f;
        float2* outp = g_h + ((size_t)(b * LSEQ + chunk * CT)) * NS + tid;
#pragma unroll 4
        for (int t = 0; t < CT; t++) {
            float xr = Bu[t * 128 + tid];
            float xi = Bu[t * 128 + 64 + tid];
            float nr = fmaf(ab.x, hr, fmaf(-ab.y, hi, xr));
            float ni = fmaf(ab.x, hi, fmaf( ab.y, hr, xi));
            hr = nr; hi = ni;
            outp[(size_t)t * NS] = make_float2(hr, hi);
        }
        g_last[(b * NC + chunk) * NS + tid] = make_float2(hr, hi);
    }
}

// ---------------- K2: cross-chunk carry scan (8 blocks, prefetched) ----------------
__global__ void k2_carry() {
    int b = blockIdx.x;          // 8 blocks
    int n = threadIdx.x;         // 64 threads
    float2 p = g_apow[CT * NS + n];
    float2 S[NC];
#pragma unroll
    for (int c = 0; c < NC; c++) S[c] = g_last[(b * NC + c) * NS + n];
    float2 H = make_float2(0.0f, 0.0f);
#pragma unroll
    for (int c = 0; c < NC; c++) {
        g_carry[(b * NC + c) * NS + n] = H;
        float2 t = cmul(p, H);
        H = make_float2(t.x + S[c].x, t.y + S[c].y);
    }
}

// ---------------- K3: register-resident readout + residual + fused LN ----------------
// 512 threads, 16 warps. Warp w owns d-slice [w*64, w*64+64) for 32 tokens.
// C fragments come straight from gmem (L2-hot). x lives in accumulators; LN via
// quad-shuffle + tiny smem cross-warp reduce.
__global__ __launch_bounds__(512, 1) void k3_readout(const float* __restrict__ u,
                                                     const float* __restrict__ Cm,
                                                     const float* __restrict__ Dv,
                                                     const float* __restrict__ gamma,
                                                     const float* __restrict__ beta,
                                                     float* __restrict__ out) {
    __shared__ float Rs[32 * 68];          // tf32 bits, [t][n]
    __shared__ float sred[32 * 16];        // row sums per warp
    __shared__ float sred2[32 * 16];
    __shared__ float smu[32], srs[32];

    int g = blockIdx.x, b = blockIdx.y;
    int chunk = g >> 2, t0 = (g & 3) * 32;
    int tid = threadIdx.x;
    int lane = tid & 31, warp = tid >> 5;
    int lq = lane >> 2, cq = lane & 3;
    int d0w = warp * 64;
    size_t tokbase = (size_t)b * LSEQ + (size_t)chunk * CT + t0;

    // build Rs[t][n] = tf32(Re(a^{t0+t+1} * H + h_local))
    {
        int n = tid & 63, tq = tid >> 6;    // 8 token groups
        float2 H = g_carry[(b * NC + chunk) * NS + n];
        const float2* hp = g_h + tokbase * NS;
#pragma unroll
        for (int t = tq; t < 32; t += 8) {
            float2 lv = hp[(size_t)t * NS + n];
            float2 pw = g_apow[(t0 + t + 1) * NS + n];
            float v = fmaf(pw.x, H.x, fmaf(-pw.y, H.y, lv.x));
            Rs[t * 68 + n] = __uint_as_float(f2tf(v));
        }
    }
    __syncthreads();

    float4 acc[2][8];
#pragma unroll
    for (int mt = 0; mt < 2; mt++)
#pragma unroll
        for (int nt = 0; nt < 8; nt++) acc[mt][nt] = make_float4(0.f, 0.f, 0.f, 0.f);

    const uint32_t* Ru = (const uint32_t*)Rs;
#pragma unroll
    for (int ks = 0; ks < 8; ks++) {
        int kb = ks * 8;
        uint32_t bf[8][2];
#pragma unroll
        for (int nt = 0; nt < 8; nt++) {
            int d = d0w + nt * 8 + lq;
            bf[nt][0] = f2tf(Cm[(size_t)d * NS + kb + cq]);
            bf[nt][1] = f2tf(Cm[(size_t)d * NS + kb + cq + 4]);
        }
        uint32_t af[2][4];
#pragma unroll
        for (int mt = 0; mt < 2; mt++) {
            int r = mt * 16 + lq;
            af[mt][0] = Ru[r * 68 + kb + cq];
            af[mt][1] = Ru[(r + 8) * 68 + kb + cq];
            af[mt][2] = Ru[r * 68 + kb + cq + 4];
            af[mt][3] = Ru[(r + 8) * 68 + kb + cq + 4];
        }
#pragma unroll
        for (int nt = 0; nt < 8; nt++) {
            mma8(acc[0][nt], af[0], bf[nt]);
            mma8(acc[1][nt], af[1], bf[nt]);
        }
    }

    // residual: acc += u * (1 + D)
#pragma unroll
    for (int nt = 0; nt < 8; nt++) {
        int d = d0w + nt * 8 + cq * 2;
        float2 D2 = *(const float2*)(Dv + d);
#pragma unroll
        for (int mt = 0; mt < 2; mt++) {
            int r1 = mt * 16 + lq;
            float2 u1 = *(const float2*)(u + (tokbase + r1) * DM + d);
            float2 u2 = *(const float2*)(u + (tokbase + r1 + 8) * DM + d);
            acc[mt][nt].x = fmaf(u1.x, 1.0f + D2.x, acc[mt][nt].x);
            acc[mt][nt].y = fmaf(u1.y, 1.0f + D2.y, acc[mt][nt].y);
            acc[mt][nt].z = fmaf(u2.x, 1.0f + D2.x, acc[mt][nt].z);
            acc[mt][nt].w = fmaf(u2.y, 1.0f + D2.y, acc[mt][nt].w);
        }
    }

    // per-row partial sums over this warp's 64-wide d-slice
    // row index i: 0 -> lq, 1 -> lq+8, 2 -> lq+16, 3 -> lq+24
    float s[4] = {0.f, 0.f, 0.f, 0.f}, q[4] = {0.f, 0.f, 0.f, 0.f};
#pragma unroll
    for (int mt = 0; mt < 2; mt++)
#pragma unroll
        for (int nt = 0; nt < 8; nt++) {
            float4 v = acc[mt][nt];
            s[mt * 2]     += v.x + v.y;
            q[mt * 2]     += v.x * v.x + v.y * v.y;
            s[mt * 2 + 1] += v.z + v.w;
            q[mt * 2 + 1] += v.z * v.z + v.w * v.w;
        }
#pragma unroll
    for (int o = 1; o <= 2; o <<= 1)
#pragma unroll
        for (int i = 0; i < 4; i++) {
            s[i] += __shfl_xor_sync(0xffffffffu, s[i], o);
            q[i] += __shfl_xor_sync(0xffffffffu, q[i], o);
        }
    if (cq == 0) {
#pragma unroll
        for (int i = 0; i < 4; i++) {
            int r = lq + i * 8;
            sred[r * 16 + warp]  = s[i];
            sred2[r * 16 + warp] = q[i];
        }
    }
    __syncthreads();
    if (tid < 32) {
        float a = 0.f, c = 0.f;
#pragma unroll
        for (int w = 0; w < 16; w++) {
            a += sred[tid * 16 + w];
            c += sred2[tid * 16 + w];
        }
        float mu = a * (1.0f / DM);
        float var = c * (1.0f / DM) - mu * mu;
        smu[tid] = mu;
        srs[tid] = rsqrtf(var + LN_EPS);
    }
    __syncthreads();

    float mu[4], rs[4];
#pragma unroll
    for (int i = 0; i < 4; i++) {
        int r = lq + i * 8;          // rows lq, lq+8, lq+16, lq+24
        mu[i] = smu[r];
        rs[i] = srs[r];
    }
    // reorder to [mt][half]: row mt*16+lq -> i = mt*2 ; row mt*16+lq+8 -> i = mt*2+1
    // mt=0: rows lq (i0), lq+8 (i1) ; mt=1: rows lq+16 (i2), lq+24 (i3)  -> identity mapping

    // normalize + write
#pragma unroll
    for (int nt = 0; nt < 8; nt++) {
        int d = d0w + nt * 8 + cq * 2;
        float2 g2 = *(const float2*)(gamma + d);
        float2 b2 = *(const float2*)(beta + d);
#pragma unroll
        for (int mt = 0; mt < 2; mt++) {
            int r1 = mt * 16 + lq;
            float4 v = acc[mt][nt];
            float mu1 = mu[mt * 2], rs1 = rs[mt * 2];
            float mu2 = mu[mt * 2 + 1], rs2 = rs[mt * 2 + 1];
            float2 o1, o2;
            o1.x = fmaf((v.x - mu1) * rs1, g2.x, b2.x);
            o1.y = fmaf((v.y - mu1) * rs1, g2.y, b2.y);
            o2.x = fmaf((v.z - mu2) * rs2, g2.x, b2.x);
            o2.y = fmaf((v.w - mu2) * rs2, g2.y, b2.y);
            *(float2*)(out + (tokbase + r1) * DM + d)     = o1;
            *(float2*)(out + (tokbase + r1 + 8) * DM + d) = o2;
        }
    }
}

// ---------------- launch ----------------
extern "C" void kernel_launch(void* const* d_in, const int* in_sizes, int n_in,
                              void* d_out, int out_size) {
    const float* u     = (const float*)d_in[0];
    const float* lnr   = (const float*)d_in[1];
    const float* imagv = (const float*)d_in[2];
    const float* Bm    = (const float*)d_in[3];
    const float* Cm    = (const float*)d_in[4];
    const float* Dv    = (const float*)d_in[5];
    const float* gamma = (const float*)d_in[6];
    const float* beta  = (const float*)d_in[7];
    float* out = (float*)d_out;

    cudaFuncSetAttribute(k1_bu_scan, cudaFuncAttributeMaxDynamicSharedMemorySize, K1_SMEM);

    k0a_consts<<<1, 64>>>(lnr, imagv);
    k0b_weights<<<128, 256>>>(Bm);
    k1_bu_scan<<<dim3(NC, BSZ), 256, K1_SMEM>>>(u);
    k2_carry<<<8, 64>>>();
    k3_readout<<<dim3(NC * 4, BSZ), 512>>>(u, Cm, Dv, gamma, beta, out);
}

// round 5
// speedup vs baseline: 2.6395x; 1.3254x over previous
#include <cuda_runtime.h>
#include <cstdint>
#include <cstddef>

// Problem constants (fixed by the dataset)
#define BSZ 8
#define LSEQ 4096
#define DM 1024
#define NS 64
#define CT 128
#define NC (LSEQ / CT)
#define LN_EPS 1e-5f

// ---------------- device scratch ----------------
__device__ float2 g_abar[NS];
__device__ float2 g_apow[(CT + 1) * NS];
__device__ float  g_W[128 * DM];                  // [j][k] tf32 bits; j<64 Re, j>=64 Im
__device__ float  g_Ct[DM * NS];                  // permuted tf32 C for k3 fragment LDG.128
__device__ float2 g_h[(size_t)BSZ * LSEQ * NS];   // within-chunk scanned states
__device__ float2 g_last[BSZ * NC * NS];          // chunk-final local states
__device__ float2 g_carry[BSZ * NC * NS];         // carry-in per chunk

__device__ __forceinline__ float2 cmul(float2 a, float2 b) {
    return make_float2(a.x * b.x - a.y * b.y, a.x * b.y + a.y * b.x);
}
__device__ __forceinline__ uint32_t f2tf(float f) {
    uint32_t r;
    asm("cvt.rna.tf32.f32 %0, %1;" : "=r"(r) : "f"(f));
    return r;
}
__device__ __forceinline__ void mma8(float4& d, const uint32_t* a, const uint32_t* b) {
    asm volatile(
        "mma.sync.aligned.m16n8k8.row.col.f32.tf32.tf32.f32 "
        "{%0,%1,%2,%3},{%4,%5,%6,%7},{%8,%9},{%0,%1,%2,%3};\n"
        : "+f"(d.x), "+f"(d.y), "+f"(d.z), "+f"(d.w)
        : "r"(a[0]), "r"(a[1]), "r"(a[2]), "r"(a[3]), "r"(b[0]), "r"(b[1]));
}

// ---------------- K0: constants + W build + C permute (single launch) ----------------
// blocks 0..127   : W[j][k] = tf32(coef_part(j) * B[j&63][k]); block 0 also writes tables
// blocks 128..383 : permuted C: g_Ct[d*64 + e], e = ksb*16 + cq*4 + ko*2 + r
//                   maps src k = 8*(2*ksb+ko) + cq + 4*r
__global__ void k0_prep(const float* __restrict__ lnr, const float* __restrict__ imag,
                        const float* __restrict__ Bm, const float* __restrict__ Cm) {
    int j = blockIdx.x;
    int tid = threadIdx.x;
    if (j < 128) {
        int n = j & 63;
        float ar = -expf(lnr[n]);
        float ai = imag[n];
        float e  = expf(ar);
        float2 abar = make_float2(e * cosf(ai), e * sinf(ai));
        float2 num = make_float2(abar.x - 1.0f, abar.y);
        float inv = 1.0f / (ar * ar + ai * ai);
        float2 coef = make_float2((num.x * ar + num.y * ai) * inv,
                                  (num.y * ar - num.x * ai) * inv);
        float s = (j < NS) ? coef.x : coef.y;
        for (int k = tid; k < DM; k += blockDim.x)
            g_W[(size_t)j * DM + k] = __uint_as_float(f2tf(s * Bm[(size_t)n * DM + k]));
        if (j == 0 && tid < NS) {
            int nn = tid;
            float ar2 = -expf(lnr[nn]);
            float ai2 = imag[nn];
            float e2  = expf(ar2);
            float2 ab = make_float2(e2 * cosf(ai2), e2 * sinf(ai2));
            g_abar[nn] = ab;
            float2 p = make_float2(1.0f, 0.0f);
            for (int k = 0; k <= CT; k++) {
                g_apow[k * NS + nn] = p;
                p = cmul(p, ab);
            }
        }
    } else {
        int c = j - 128;                  // 0..255, 4 d-rows each
        int d = c * 4 + (tid >> 6);
        int e = tid & 63;
        int ksb = e >> 4, rem = e & 15;
        int cq = rem >> 2, ko = (rem >> 1) & 1, r = rem & 1;
        int k = 8 * (2 * ksb + ko) + cq + 4 * r;
        g_Ct[(size_t)d * NS + e] = __uint_as_float(f2tf(Cm[(size_t)d * NS + k]));
    }
}

// ---------------- K1: tf32 MMA Bu-GEMM (128x128, K=1024) + local scan ----------------
#define KC 32
#define ASTR 36
// smem words: As(2x128x36) + Bs(2x128x36) = 18432 words; Bu (16384 words) aliases As/Bs
#define K1_SMEM (18432 * 4)

__global__ __launch_bounds__(256, 2) void k1_bu_scan(const float* __restrict__ u) {
    extern __shared__ float sm[];
    float* As0 = sm;
    float* As1 = sm + 128 * ASTR;
    float* Bs0 = sm + 2 * 128 * ASTR;
    float* Bs1 = sm + 3 * 128 * ASTR;
    float* Bu  = sm;                      // alias: As/Bs dead after mainloop

    int chunk = blockIdx.x, b = blockIdx.y;
    int tid = threadIdx.x;
    int lane = tid & 31, warp = tid >> 5;
    int wm = warp & 1, wn = warp >> 1;
    int m0 = wm * 64, n0 = wn * 32;
    int lq = lane >> 2, cq = lane & 3;

    const float* up = u + ((size_t)(b * LSEQ + chunk * CT)) * DM;

    float4 acc[4][4];
#pragma unroll
    for (int i = 0; i < 4; i++)
#pragma unroll
        for (int j = 0; j < 4; j++) acc[i][j] = make_float4(0.f, 0.f, 0.f, 0.f);

    float4 rA[4], rB[4];
    int lrow[4], lkq[4];
#pragma unroll
    for (int i = 0; i < 4; i++) {
        int lin = tid + i * 256;
        lrow[i] = lin >> 3;
        lkq[i] = (lin & 7) * 4;
    }

    // preload stage 0
#pragma unroll
    for (int i = 0; i < 4; i++) {
        rA[i] = *(const float4*)(up + (size_t)lrow[i] * DM + lkq[i]);
        rB[i] = *(const float4*)(g_W + (size_t)lrow[i] * DM + lkq[i]);
    }
#pragma unroll
    for (int i = 0; i < 4; i++) {
        uint4 a;
        a.x = f2tf(rA[i].x); a.y = f2tf(rA[i].y); a.z = f2tf(rA[i].z); a.w = f2tf(rA[i].w);
        *(uint4*)(As0 + lrow[i] * ASTR + lkq[i]) = a;
        *(float4*)(Bs0 + lrow[i] * ASTR + lkq[i]) = rB[i];
    }
    __syncthreads();

    for (int s = 0; s < DM / KC; s++) {
        float* Ac = (s & 1) ? As1 : As0;
        float* Bc = (s & 1) ? Bs1 : Bs0;
        float* An = (s & 1) ? As0 : As1;
        float* Bn = (s & 1) ? Bs0 : Bs1;
        if (s + 1 < DM / KC) {
            int k0 = (s + 1) * KC;
#pragma unroll
            for (int i = 0; i < 4; i++) {
                rA[i] = *(const float4*)(up + (size_t)lrow[i] * DM + k0 + lkq[i]);
                rB[i] = *(const float4*)(g_W + (size_t)lrow[i] * DM + k0 + lkq[i]);
            }
        }
        const uint32_t* Au = (const uint32_t*)Ac;
        const uint32_t* Bv = (const uint32_t*)Bc;
#pragma unroll
        for (int ks = 0; ks < 4; ks++) {
            int kb = ks * 8;
            uint32_t af[4][4], bf[4][2];
#pragma unroll
            for (int mt = 0; mt < 4; mt++) {
                int r = m0 + mt * 16 + lq;
                af[mt][0] = Au[r * ASTR + kb + cq];
                af[mt][1] = Au[(r + 8) * ASTR + kb + cq];
                af[mt][2] = Au[r * ASTR + kb + cq + 4];
                af[mt][3] = Au[(r + 8) * ASTR + kb + cq + 4];
            }
#pragma unroll
            for (int nt = 0; nt < 4; nt++) {
                int c = n0 + nt * 8 + lq;
                bf[nt][0] = Bv[c * ASTR + kb + cq];
                bf[nt][1] = Bv[c * ASTR + kb + cq + 4];
            }
#pragma unroll
            for (int mt = 0; mt < 4; mt++)
#pragma unroll
                for (int nt = 0; nt < 4; nt++)
                    mma8(acc[mt][nt], af[mt], bf[nt]);
        }
        if (s + 1 < DM / KC) {
#pragma unroll
            for (int i = 0; i < 4; i++) {
                uint4 a;
                a.x = f2tf(rA[i].x); a.y = f2tf(rA[i].y); a.z = f2tf(rA[i].z); a.w = f2tf(rA[i].w);
                *(uint4*)(An + lrow[i] * ASTR + lkq[i]) = a;
                *(float4*)(Bn + lrow[i] * ASTR + lkq[i]) = rB[i];
            }
        }
        __syncthreads();
    }

    // write Bu tile to smem (aliases As/Bs — safe: all fragment reads done at last sync)
#pragma unroll
    for (int mt = 0; mt < 4; mt++) {
        int r = m0 + mt * 16 + lq;
#pragma unroll
        for (int nt = 0; nt < 4; nt++) {
            int c = n0 + nt * 8 + cq * 2;
            *(float2*)(Bu + r * 128 + c)       = make_float2(acc[mt][nt].x, acc[mt][nt].y);
            *(float2*)(Bu + (r + 8) * 128 + c) = make_float2(acc[mt][nt].z, acc[mt][nt].w);
        }
    }
    __syncthreads();

    // local scan: 64 states, 1 thread each
    if (tid < NS) {
        float2 ab = g_abar[tid];
        float hr = 0.0f, hi = 0.0f;
        float2* outp = g_h + ((size_t)(b * LSEQ + chunk * CT)) * NS + tid;
#pragma unroll 4
        for (int t = 0; t < CT; t++) {
            float xr = Bu[t * 128 + tid];
            float xi = Bu[t * 128 + 64 + tid];
            float nr = fmaf(ab.x, hr, fmaf(-ab.y, hi, xr));
            float ni = fmaf(ab.x, hi, fmaf( ab.y, hr, xi));
            hr = nr; hi = ni;
            outp[(size_t)t * NS] = make_float2(hr, hi);
        }
        g_last[(b * NC + chunk) * NS + tid] = make_float2(hr, hi);
    }
}

// ---------------- K2: cross-chunk carry scan (8 blocks, prefetched) ----------------
__global__ void k2_carry() {
    int b = blockIdx.x;          // 8 blocks
    int n = threadIdx.x;         // 64 threads
    float2 p = g_apow[CT * NS + n];
    float2 S[NC];
#pragma unroll
    for (int c = 0; c < NC; c++) S[c] = g_last[(b * NC + c) * NS + n];
    float2 H = make_float2(0.0f, 0.0f);
#pragma unroll
    for (int c = 0; c < NC; c++) {
        g_carry[(b * NC + c) * NS + n] = H;
        float2 t = cmul(p, H);
        H = make_float2(t.x + S[c].x, t.y + S[c].y);
    }
}

// ---------------- K3: register-resident readout + residual + fused LN ----------------
// 512 threads, 16 warps. Warp w owns d-slice [w*64, w*64+64) for 32 tokens.
// C fragments load as coalesced LDG.128 from the permuted g_Ct.
__global__ __launch_bounds__(512, 1) void k3_readout(const float* __restrict__ u,
                                                     const float* __restrict__ Dv,
                                                     const float* __restrict__ gamma,
                                                     const float* __restrict__ beta,
                                                     float* __restrict__ out) {
    __shared__ float Rs[32 * 68];          // tf32 bits, [t][n]
    __shared__ float sred[32 * 16];
    __shared__ float sred2[32 * 16];
    __shared__ float smu[32], srs[32];

    int g = blockIdx.x, b = blockIdx.y;
    int chunk = g >> 2, t0 = (g & 3) * 32;
    int tid = threadIdx.x;
    int lane = tid & 31, warp = tid >> 5;
    int lq = lane >> 2, cq = lane & 3;
    int d0w = warp * 64;
    size_t tokbase = (size_t)b * LSEQ + (size_t)chunk * CT + t0;

    // build Rs[t][n] = tf32(Re(a^{t0+t+1} * H + h_local))
    {
        int n = tid & 63, tq = tid >> 6;    // 8 token groups
        float2 H = g_carry[(b * NC + chunk) * NS + n];
        const float2* hp = g_h + tokbase * NS;
#pragma unroll
        for (int t = tq; t < 32; t += 8) {
            float2 lv = hp[(size_t)t * NS + n];
            float2 pw = g_apow[(t0 + t + 1) * NS + n];
            float v = fmaf(pw.x, H.x, fmaf(-pw.y, H.y, lv.x));
            Rs[t * 68 + n] = __uint_as_float(f2tf(v));
        }
    }
    __syncthreads();

    float4 acc[2][8];
#pragma unroll
    for (int mt = 0; mt < 2; mt++)
#pragma unroll
        for (int nt = 0; nt < 8; nt++) acc[mt][nt] = make_float4(0.f, 0.f, 0.f, 0.f);

    const uint32_t* Ru = (const uint32_t*)Rs;
    const uint4* Ct = (const uint4*)g_Ct;   // row d -> 16 uint4; [d*16 + ksb*4 + cq]

#pragma unroll
    for (int ksb = 0; ksb < 4; ksb++) {
        // A fragments for ks = 2*ksb, 2*ksb+1
        uint32_t af[2][2][4];
#pragma unroll
        for (int ko = 0; ko < 2; ko++) {
            int kb = (ksb * 2 + ko) * 8;
#pragma unroll
            for (int mt = 0; mt < 2; mt++) {
                int r = mt * 16 + lq;
                af[ko][mt][0] = Ru[r * 68 + kb + cq];
                af[ko][mt][1] = Ru[(r + 8) * 68 + kb + cq];
                af[ko][mt][2] = Ru[r * 68 + kb + cq + 4];
                af[ko][mt][3] = Ru[(r + 8) * 68 + kb + cq + 4];
            }
        }
        uint4 Cf = Ct[(size_t)(d0w + lq) * 16 + ksb * 4 + cq];
#pragma unroll
        for (int nt = 0; nt < 8; nt++) {
            uint4 cur = Cf;
            if (nt < 7)
                Cf = Ct[(size_t)(d0w + (nt + 1) * 8 + lq) * 16 + ksb * 4 + cq];
            uint32_t b0[2] = {cur.x, cur.y};
            uint32_t b1[2] = {cur.z, cur.w};
#pragma unroll
            for (int mt = 0; mt < 2; mt++) {
                mma8(acc[mt][nt], af[0][mt], b0);
                mma8(acc[mt][nt], af[1][mt], b1);
            }
        }
    }

    // residual: acc += u * (1 + D)
#pragma unroll
    for (int nt = 0; nt < 8; nt++) {
        int d = d0w + nt * 8 + cq * 2;
        float2 D2 = *(const float2*)(Dv + d);
#pragma unroll
        for (int mt = 0; mt < 2; mt++) {
            int r1 = mt * 16 + lq;
            float2 u1 = *(const float2*)(u + (tokbase + r1) * DM + d);
            float2 u2 = *(const float2*)(u + (tokbase + r1 + 8) * DM + d);
            acc[mt][nt].x = fmaf(u1.x, 1.0f + D2.x, acc[mt][nt].x);
            acc[mt][nt].y = fmaf(u1.y, 1.0f + D2.y, acc[mt][nt].y);
            acc[mt][nt].z = fmaf(u2.x, 1.0f + D2.x, acc[mt][nt].z);
            acc[mt][nt].w = fmaf(u2.y, 1.0f + D2.y, acc[mt][nt].w);
        }
    }

    // per-row partial sums over this warp's 64-wide d-slice
    float s[4] = {0.f, 0.f, 0.f, 0.f}, q[4] = {0.f, 0.f, 0.f, 0.f};
#pragma unroll
    for (int mt = 0; mt < 2; mt++)
#pragma unroll
        for (int nt = 0; nt < 8; nt++) {
            float4 v = acc[mt][nt];
            s[mt * 2]     += v.x + v.y;
            q[mt * 2]     += v.x * v.x + v.y * v.y;
            s[mt * 2 + 1] += v.z + v.w;
            q[mt * 2 + 1] += v.z * v.z + v.w * v.w;
        }
#pragma unroll
    for (int o = 1; o <= 2; o <<= 1)
#pragma unroll
        for (int i = 0; i < 4; i++) {
            s[i] += __shfl_xor_sync(0xffffffffu, s[i], o);
            q[i] += __shfl_xor_sync(0xffffffffu, q[i], o);
        }
    if (cq == 0) {
#pragma unroll
        for (int i = 0; i < 4; i++) {
            int r = lq + i * 8;
            sred[r * 16 + warp]  = s[i];
            sred2[r * 16 + warp] = q[i];
        }
    }
    __syncthreads();
    if (tid < 32) {
        float a = 0.f, c = 0.f;
#pragma unroll
        for (int w = 0; w < 16; w++) {
            a += sred[tid * 16 + w];
            c += sred2[tid * 16 + w];
        }
        float mu = a * (1.0f / DM);
        float var = c * (1.0f / DM) - mu * mu;
        smu[tid] = mu;
        srs[tid] = rsqrtf(var + LN_EPS);
    }
    __syncthreads();

    float mu[4], rs[4];
#pragma unroll
    for (int i = 0; i < 4; i++) {
        int r = lq + i * 8;
        mu[i] = smu[r];
        rs[i] = srs[r];
    }

    // normalize + write
#pragma unroll
    for (int nt = 0; nt < 8; nt++) {
        int d = d0w + nt * 8 + cq * 2;
        float2 g2 = *(const float2*)(gamma + d);
        float2 b2 = *(const float2*)(beta + d);
#pragma unroll
        for (int mt = 0; mt < 2; mt++) {
            int r1 = mt * 16 + lq;
            float4 v = acc[mt][nt];
            float mu1 = mu[mt * 2], rs1 = rs[mt * 2];
            float mu2 = mu[mt * 2 + 1], rs2 = rs[mt * 2 + 1];
            float2 o1, o2;
            o1.x = fmaf((v.x - mu1) * rs1, g2.x, b2.x);
            o1.y = fmaf((v.y - mu1) * rs1, g2.y, b2.y);
            o2.x = fmaf((v.z - mu2) * rs2, g2.x, b2.x);
            o2.y = fmaf((v.w - mu2) * rs2, g2.y, b2.y);
            *(float2*)(out + (tokbase + r1) * DM + d)     = o1;
            *(float2*)(out + (tokbase + r1 + 8) * DM + d) = o2;
        }
    }
}

// ---------------- launch ----------------
extern "C" void kernel_launch(void* const* d_in, const int* in_sizes, int n_in,
                              void* d_out, int out_size) {
    const float* u     = (const float*)d_in[0];
    const float* lnr   = (const float*)d_in[1];
    const float* imagv = (const float*)d_in[2];
    const float* Bm    = (const float*)d_in[3];
    const float* Cm    = (const float*)d_in[4];
    const float* Dv    = (const float*)d_in[5];
    const float* gamma = (const float*)d_in[6];
    const float* beta  = (const float*)d_in[7];
    float* out = (float*)d_out;

    cudaFuncSetAttribute(k1_bu_scan, cudaFuncAttributeMaxDynamicSharedMemorySize, K1_SMEM);

    k0_prep<<<384, 256>>>(lnr, imagv, Bm, Cm);
    k1_bu_scan<<<dim3(NC, BSZ), 256, K1_SMEM>>>(u);
    k2_carry<<<8, 64>>>();
    k3_readout<<<dim3(NC * 4, BSZ), 512>>>(u, Dv, gamma, beta, out);
}